// round 12
// baseline (speedup 1.0000x reference)
#include <cuda_runtime.h>
#include <cuda_fp16.h>
#include <math.h>

#define NMAX 50000
#define EMAX 1600000

// ---------------- static device scratch ----------------
__device__ float  g_fs[NMAX * 188];     // projected features fs (fp32, max F=188)
__device__ __half g_fsh[NMAX * 192];    // fp16 gather table (L0/1: [N,128]; L2: [N,4*48] padded)
__device__ float  g_act0[NMAX * 128];
__device__ float  g_act1[NMAX * 128];
__device__ float  g_out2[NMAX * 188];
__device__ float  g_el[NMAX * 4];
__device__ float  g_er[NMAX * 4];
__device__ float  g_e[EMAX * 4];        // exp(edge logit) scratch [E,H] (layer 2 only)
__device__ int    g_csrc[EMAX];
__device__ int    g_rowptr[NMAX + 1];
__device__ int    g_cnt[NMAX];
__device__ int    g_cursor[NMAX];

__device__ __forceinline__ float lrelu(float x) { return x >= 0.f ? x : 0.2f * x; }

// ---- packed fp32x2 FMA (sm_103a; bit-exact: rn per half) ----
__device__ __forceinline__ void ffma2(unsigned long long& c, unsigned long long a,
                                      unsigned long long b) {
    asm("fma.rn.f32x2 %0, %1, %2, %0;" : "+l"(c) : "l"(a), "l"(b));
}
__device__ __forceinline__ unsigned long long pk2(float x) {
    unsigned long long r;
    asm("mov.b64 %0, {%1, %1};" : "=l"(r) : "f"(x));
    return r;
}
__device__ __forceinline__ float2 upk2(unsigned long long v) {
    float2 f;
    asm("mov.b64 {%0, %1}, %2;" : "=f"(f.x), "=f"(f.y) : "l"(v));
    return f;
}

#define WSUM(s) do {                                          \
    _Pragma("unroll")                                         \
    for (int off = 16; off; off >>= 1)                        \
        (s) += __shfl_xor_sync(0xffffffffu, (s), off);        \
} while (0)

// ---------------- CSR construction ----------------
__global__ void hist_kernel(const int* __restrict__ dst, int E) {
    int b = (blockIdx.x * blockDim.x + threadIdx.x) * 4;
    if (b + 3 < E) {
        int4 d = *(const int4*)(dst + b);
        atomicAdd(&g_cnt[d.x], 1);
        atomicAdd(&g_cnt[d.y], 1);
        atomicAdd(&g_cnt[d.z], 1);
        atomicAdd(&g_cnt[d.w], 1);
    } else {
        for (int e = b; e < E; e++) atomicAdd(&g_cnt[dst[e]], 1);
    }
}

__global__ void scan_kernel(int n, int E) {
    const int T = 1024;
    __shared__ int sh[T];
    int tid = threadIdx.x;
    int chunk = (n + T - 1) / T;
    int start = tid * chunk;
    int stop  = min(start + chunk, n);
    int sum = 0;
    for (int i = start; i < stop; i++) sum += g_cnt[i];
    sh[tid] = sum;
    __syncthreads();
    for (int off = 1; off < T; off <<= 1) {
        int v = (tid >= off) ? sh[tid - off] : 0;
        __syncthreads();
        sh[tid] += v;
        __syncthreads();
    }
    int run = sh[tid] - sum;
    for (int i = start; i < stop; i++) {
        g_rowptr[i] = run;
        g_cursor[i] = run;
        run += g_cnt[i];
    }
    if (tid == 0) g_rowptr[n] = E;
}

__global__ void scatter_kernel(const int* __restrict__ src, const int* __restrict__ dst, int E) {
    int b = (blockIdx.x * blockDim.x + threadIdx.x) * 4;
    if (b + 3 < E) {
        int4 s = *(const int4*)(src + b);
        int4 d = *(const int4*)(dst + b);
        int p0 = atomicAdd(&g_cursor[d.x], 1);
        int p1 = atomicAdd(&g_cursor[d.y], 1);
        int p2 = atomicAdd(&g_cursor[d.z], 1);
        int p3 = atomicAdd(&g_cursor[d.w], 1);
        g_csrc[p0] = s.x; g_csrc[p1] = s.y;
        g_csrc[p2] = s.z; g_csrc[p3] = s.w;
    } else {
        for (int e = b; e < E; e++) {
            int p = atomicAdd(&g_cursor[dst[e]], 1);
            g_csrc[p] = src[e];
        }
    }
}

// ---------------- double-buffered register-tiled GEMM (+optional fp16 copy) ----------------
template <int K, int F, bool HOUT>
__global__ void gemm128_kernel(const float* __restrict__ A, const float* __restrict__ W,
                               float* __restrict__ out, __half* __restrict__ outh, int n) {
    __shared__ float As[16][128];
    __shared__ float Ws[16][64];
    const int t  = threadIdx.x;
    const int tx = t & 7;
    const int ty = t >> 3;
    const int m0 = blockIdx.x * 128;
    const int f0 = blockIdx.y * 64;

    unsigned long long acc[8][4];
#pragma unroll
    for (int i = 0; i < 8; i++)
#pragma unroll
        for (int j = 0; j < 4; j++) acc[i][j] = 0ull;

    float4 pA[4], pW[2];

    auto loadA = [&](int k0) {
#pragma unroll
        for (int i = 0; i < 4; i++) {
            int fid = i * 128 + t;
            int m = fid >> 2, kq = fid & 3;
            int row = m0 + m, k = k0 + kq * 4;
            float4 v = make_float4(0.f, 0.f, 0.f, 0.f);
            if (row < n && k < K) {
                const float* p = A + (long)row * K + k;
                if (k + 3 < K) v = *(const float4*)p;
                else {
                    v.x = p[0];
                    if (k + 1 < K) v.y = p[1];
                    if (k + 2 < K) v.z = p[2];
                }
            }
            pA[i] = v;
        }
    };
    auto loadW = [&](int k0) {
#pragma unroll
        for (int i = 0; i < 2; i++) {
            int fid = i * 128 + t;
            int krow = fid >> 4, fq = fid & 15;
            int k = k0 + krow, f = f0 + fq * 4;
            float4 v = make_float4(0.f, 0.f, 0.f, 0.f);
            if (k < K) {
                const float* p = W + (long)k * F + f;
                if (f + 3 < F) v = *(const float4*)p;
                else {
                    if (f + 0 < F) v.x = p[0];
                    if (f + 1 < F) v.y = p[1];
                    if (f + 2 < F) v.z = p[2];
                }
            }
            pW[i] = v;
        }
    };
    auto storeTiles = [&]() {
#pragma unroll
        for (int i = 0; i < 4; i++) {
            int fid = i * 128 + t;
            int m = fid >> 2, kq = fid & 3;
            As[kq * 4 + 0][m] = pA[i].x;
            As[kq * 4 + 1][m] = pA[i].y;
            As[kq * 4 + 2][m] = pA[i].z;
            As[kq * 4 + 3][m] = pA[i].w;
        }
#pragma unroll
        for (int i = 0; i < 2; i++) {
            int fid = i * 128 + t;
            int krow = fid >> 4, fq = fid & 15;
            *(float4*)&Ws[krow][fq * 4] = pW[i];
        }
    };

    loadA(0);
    loadW(0);
    for (int k0 = 0; k0 < K; k0 += 16) {
        storeTiles();
        __syncthreads();
        if (k0 + 16 < K) {
            loadA(k0 + 16);
            loadW(k0 + 16);
        }
#pragma unroll
        for (int k = 0; k < 16; k++) {
            float a[8];
            *(float4*)(a + 0) = *(const float4*)&As[k][ty * 8 + 0];
            *(float4*)(a + 4) = *(const float4*)&As[k][ty * 8 + 4];
            ulonglong2 b01 = *(const ulonglong2*)&Ws[k][tx * 8 + 0];
            ulonglong2 b23 = *(const ulonglong2*)&Ws[k][tx * 8 + 4];
#pragma unroll
            for (int im = 0; im < 8; im++) {
                unsigned long long pa = pk2(a[im]);
                ffma2(acc[im][0], pa, b01.x);
                ffma2(acc[im][1], pa, b01.y);
                ffma2(acc[im][2], pa, b23.x);
                ffma2(acc[im][3], pa, b23.y);
            }
        }
        __syncthreads();
    }
#pragma unroll
    for (int im = 0; im < 8; im++) {
        int row = m0 + ty * 8 + im;
        if (row >= n) continue;
        float* po = out + (long)row * F + f0 + tx * 8;
        if (f0 + tx * 8 + 7 < F) {
            ((ulonglong2*)po)[0] = make_ulonglong2(acc[im][0], acc[im][1]);
            ((ulonglong2*)po)[1] = make_ulonglong2(acc[im][2], acc[im][3]);
            if (HOUT) {
                __half2 h0 = __float22half2_rn(upk2(acc[im][0]));
                __half2 h1 = __float22half2_rn(upk2(acc[im][1]));
                __half2 h2 = __float22half2_rn(upk2(acc[im][2]));
                __half2 h3 = __float22half2_rn(upk2(acc[im][3]));
                uint4 pkd;
                pkd.x = *(unsigned*)&h0; pkd.y = *(unsigned*)&h1;
                pkd.z = *(unsigned*)&h2; pkd.w = *(unsigned*)&h3;
                *(uint4*)(outh + (long)row * F + f0 + tx * 8) = pkd;
            }
        } else {
#pragma unroll
            for (int p = 0; p < 4; p++) {
                float2 f2 = upk2(acc[im][p]);
                if (f0 + tx * 8 + 2 * p + 0 < F) po[2 * p + 0] = f2.x;
                if (f0 + tx * 8 + 2 * p + 1 < F) po[2 * p + 1] = f2.y;
            }
        }
    }
}

// ---------------- layer-2 fp16 table: [N, 4 heads x 48], pad col zeroed ----------------
__global__ void cvt188_kernel(const float* __restrict__ fs, __half* __restrict__ fsh, int n) {
    int idx = blockIdx.x * blockDim.x + threadIdx.x;   // n*96 half2 slots
    if (idx >= n * 96) return;
    int node = idx / 96, p = idx - node * 96;
    int h = p / 24, c2 = p - h * 24;
    int c0 = 2 * c2;
    float v0 = (c0 + 0 < 47) ? fs[node * 188 + h * 47 + c0 + 0] : 0.f;
    float v1 = (c0 + 1 < 47) ? fs[node * 188 + h * 47 + c0 + 1] : 0.f;
    *(__half2*)(fsh + (long)node * 192 + h * 48 + c0) = __floats2half2_rn(v0, v1);
}

// ---------------- el/er ----------------
__global__ void elr_kernel(const float* __restrict__ fs, const float* __restrict__ al,
                           const float* __restrict__ ar, int n, int Dd, int F) {
    int idx = blockIdx.x * blockDim.x + threadIdx.x;
    if (idx >= n * 4) return;
    int node = idx >> 2, h = idx & 3;
    const float* row = fs + node * F + h * Dd;
    const float* a1  = al + h * Dd;
    const float* a2  = ar + h * Dd;
    float se = 0.f, sr = 0.f;
#pragma unroll 8
    for (int d = 0; d < Dd; d++) {
        float v = row[d];
        se = fmaf(v, a1[d], se);
        sr = fmaf(v, a2[d], sr);
    }
    g_el[idx] = se;
    g_er[idx] = sr;
}

// ---------------- fused single-pass aggregation, F=128, fp16 gather ----------------
__global__ void agg128_kernel(const __half* __restrict__ fsh, float* __restrict__ out,
                              int n, int dorelu) {
    int warp = (blockIdx.x * blockDim.x + threadIdx.x) >> 5;
    int lane = threadIdx.x & 31;
    if (warp >= n) return;
    int beg = g_rowptr[warp], end = g_rowptr[warp + 1];
    int h = lane >> 3;
    float er_h = g_er[warp * 4 + h];

    float s = 0.f;
    float4 acc = make_float4(0.f, 0.f, 0.f, 0.f);
    int j = beg;
    for (; j + 4 <= end; j += 4) {
        int sc[4];
#pragma unroll
        for (int q = 0; q < 4; q++) sc[q] = g_csrc[j + q];
        float el[4];
#pragma unroll
        for (int q = 0; q < 4; q++) el[q] = g_el[sc[q] * 4 + h];
        uint2 r[4];
#pragma unroll
        for (int q = 0; q < 4; q++) r[q] = *(const uint2*)(fsh + (long)sc[q] * 128 + lane * 4);
#pragma unroll
        for (int q = 0; q < 4; q++) {
            float x = __expf(lrelu(el[q] + er_h));
            s += x;
            float2 lo = __half22float2(*(__half2*)&r[q].x);
            float2 hi = __half22float2(*(__half2*)&r[q].y);
            acc.x = fmaf(x, lo.x, acc.x);
            acc.y = fmaf(x, lo.y, acc.y);
            acc.z = fmaf(x, hi.x, acc.z);
            acc.w = fmaf(x, hi.y, acc.w);
        }
    }
    for (; j < end; j++) {
        int sc = g_csrc[j];
        float x = __expf(lrelu(g_el[sc * 4 + h] + er_h));
        s += x;
        uint2 r = *(const uint2*)(fsh + (long)sc * 128 + lane * 4);
        float2 lo = __half22float2(*(__half2*)&r.x);
        float2 hi = __half22float2(*(__half2*)&r.y);
        acc.x = fmaf(x, lo.x, acc.x);
        acc.y = fmaf(x, lo.y, acc.y);
        acc.z = fmaf(x, hi.x, acc.z);
        acc.w = fmaf(x, hi.y, acc.w);
    }
    float ish = s > 0.f ? 1.f / s : 0.f;
    acc.x *= ish; acc.y *= ish; acc.z *= ish; acc.w *= ish;
    if (dorelu) {
        acc.x = fmaxf(acc.x, 0.f); acc.y = fmaxf(acc.y, 0.f);
        acc.z = fmaxf(acc.z, 0.f); acc.w = fmaxf(acc.w, 0.f);
    }
    *(float4*)(out + warp * 128 + lane * 4) = acc;
}

// ---------------- aggregation, F=188: two-phase, fp16 gather (fixed lane map) ----------
// 48 groups of 4 padded cols (12 per head). lane g handles group lane; lanes 0-15
// also handle group lane+32. No out-of-range groups (R4 bug fixed).
__global__ void agg188_kernel(const __half* __restrict__ fsh, float* __restrict__ out, int n) {
    int warp = (blockIdx.x * blockDim.x + threadIdx.x) >> 5;
    int lane = threadIdx.x & 31;
    if (warp >= n) return;
    int beg = g_rowptr[warp], end = g_rowptr[warp + 1];
    float4 er4 = *(const float4*)(g_er + warp * 4);

    float s0 = 0.f, s1 = 0.f, s2 = 0.f, s3 = 0.f;
    for (int j = beg + lane; j < end; j += 32) {
        int sc = g_csrc[j];
        float4 el4 = *(const float4*)(g_el + sc * 4);
        float x0 = __expf(lrelu(el4.x + er4.x));
        float x1 = __expf(lrelu(el4.y + er4.y));
        float x2 = __expf(lrelu(el4.z + er4.z));
        float x3 = __expf(lrelu(el4.w + er4.w));
        *(float4*)(g_e + 4 * j) = make_float4(x0, x1, x2, x3);
        s0 += x0; s1 += x1; s2 += x2; s3 += x3;
    }
    WSUM(s0); WSUM(s1); WSUM(s2); WSUM(s3);
    __syncwarp();

    float i0 = s0 > 0.f ? 1.f / s0 : 0.f;
    float i1 = s1 > 0.f ? 1.f / s1 : 0.f;
    float i2 = s2 > 0.f ? 1.f / s2 : 0.f;
    float i3 = s3 > 0.f ? 1.f / s3 : 0.f;

    int gA = lane;                 // 0..31, head hA = gA/12 in 0..2
    int hA = gA / 12;
    bool hasB = lane < 16;
    int gB = lane + 32;            // 32..47, head hB in 2..3
    int hB = gB / 12;
    float accA[4] = {0.f, 0.f, 0.f, 0.f};
    float accB[4] = {0.f, 0.f, 0.f, 0.f};
    int j = beg;
    for (; j + 2 <= end; j += 2) {
        int sc0 = g_csrc[j];
        int sc1 = g_csrc[j + 1];
        float4 av0 = *(const float4*)(g_e + 4 * j);
        float4 av1 = *(const float4*)(g_e + 4 * j + 4);
        const __half* r0 = fsh + (long)sc0 * 192;
        const __half* r1 = fsh + (long)sc1 * 192;
        uint2 pA0 = *(const uint2*)(r0 + gA * 4);
        uint2 pA1 = *(const uint2*)(r1 + gA * 4);
        uint2 pB0, pB1;
        if (hasB) {
            pB0 = *(const uint2*)(r0 + gB * 4);
            pB1 = *(const uint2*)(r1 + gB * 4);
        }
        float aA0 = hA == 0 ? av0.x : hA == 1 ? av0.y : hA == 2 ? av0.z : av0.w;
        float aA1 = hA == 0 ? av1.x : hA == 1 ? av1.y : hA == 2 ? av1.z : av1.w;
        {
            float2 lo = __half22float2(*(__half2*)&pA0.x);
            float2 hi = __half22float2(*(__half2*)&pA0.y);
            accA[0] = fmaf(aA0, lo.x, accA[0]); accA[1] = fmaf(aA0, lo.y, accA[1]);
            accA[2] = fmaf(aA0, hi.x, accA[2]); accA[3] = fmaf(aA0, hi.y, accA[3]);
            lo = __half22float2(*(__half2*)&pA1.x);
            hi = __half22float2(*(__half2*)&pA1.y);
            accA[0] = fmaf(aA1, lo.x, accA[0]); accA[1] = fmaf(aA1, lo.y, accA[1]);
            accA[2] = fmaf(aA1, hi.x, accA[2]); accA[3] = fmaf(aA1, hi.y, accA[3]);
        }
        if (hasB) {
            float aB0 = hB == 2 ? av0.z : av0.w;
            float aB1 = hB == 2 ? av1.z : av1.w;
            float2 lo = __half22float2(*(__half2*)&pB0.x);
            float2 hi = __half22float2(*(__half2*)&pB0.y);
            accB[0] = fmaf(aB0, lo.x, accB[0]); accB[1] = fmaf(aB0, lo.y, accB[1]);
            accB[2] = fmaf(aB0, hi.x, accB[2]); accB[3] = fmaf(aB0, hi.y, accB[3]);
            lo = __half22float2(*(__half2*)&pB1.x);
            hi = __half22float2(*(__half2*)&pB1.y);
            accB[0] = fmaf(aB1, lo.x, accB[0]); accB[1] = fmaf(aB1, lo.y, accB[1]);
            accB[2] = fmaf(aB1, hi.x, accB[2]); accB[3] = fmaf(aB1, hi.y, accB[3]);
        }
    }
    if (j < end) {
        int sc = g_csrc[j];
        float4 av = *(const float4*)(g_e + 4 * j);
        const __half* r0 = fsh + (long)sc * 192;
        uint2 pA = *(const uint2*)(r0 + gA * 4);
        float aA = hA == 0 ? av.x : hA == 1 ? av.y : hA == 2 ? av.z : av.w;
        float2 lo = __half22float2(*(__half2*)&pA.x);
        float2 hi = __half22float2(*(__half2*)&pA.y);
        accA[0] = fmaf(aA, lo.x, accA[0]); accA[1] = fmaf(aA, lo.y, accA[1]);
        accA[2] = fmaf(aA, hi.x, accA[2]); accA[3] = fmaf(aA, hi.y, accA[3]);
        if (hasB) {
            uint2 pB = *(const uint2*)(r0 + gB * 4);
            float aB = hB == 2 ? av.z : av.w;
            lo = __half22float2(*(__half2*)&pB.x);
            hi = __half22float2(*(__half2*)&pB.y);
            accB[0] = fmaf(aB, lo.x, accB[0]); accB[1] = fmaf(aB, lo.y, accB[1]);
            accB[2] = fmaf(aB, hi.x, accB[2]); accB[3] = fmaf(aB, hi.y, accB[3]);
        }
    }
    {
        float ish = hA == 0 ? i0 : hA == 1 ? i1 : hA == 2 ? i2 : i3;
        int cb = (gA - hA * 12) * 4;
        float* po = out + (long)warp * 188 + hA * 47 + cb;
#pragma unroll
        for (int i = 0; i < 4; i++)
            if (cb + i < 47) po[i] = accA[i] * ish;
    }
    if (hasB) {
        float ish = hB == 2 ? i2 : i3;
        int cb = (gB - hB * 12) * 4;
        float* po = out + (long)warp * 188 + hB * 47 + cb;
#pragma unroll
        for (int i = 0; i < 4; i++)
            if (cb + i < 47) po[i] = accB[i] * ish;
    }
}

// ---------------- head mean + log_softmax ----------------
__global__ void final_kernel(const float* __restrict__ o2, float* __restrict__ out, int n) {
    int warp = (blockIdx.x * blockDim.x + threadIdx.x) >> 5;
    int lane = threadIdx.x & 31;
    if (warp >= n) return;
    const float* base = o2 + warp * 188;
    int c1 = lane;
    int c2 = lane + 32;
    bool v2 = c2 < 47;
    float z1 = 0.25f * (base[c1] + base[47 + c1] + base[94 + c1] + base[141 + c1]);
    float z2 = v2 ? 0.25f * (base[c2] + base[47 + c2] + base[94 + c2] + base[141 + c2]) : -INFINITY;
    float mx = fmaxf(z1, z2);
#pragma unroll
    for (int off = 16; off; off >>= 1)
        mx = fmaxf(mx, __shfl_xor_sync(0xffffffffu, mx, off));
    float se = __expf(z1 - mx) + (v2 ? __expf(z2 - mx) : 0.f);
#pragma unroll
    for (int off = 16; off; off >>= 1)
        se += __shfl_xor_sync(0xffffffffu, se, off);
    float lse = mx + logf(se);
    out[warp * 47 + c1] = z1 - lse;
    if (v2) out[warp * 47 + c2] = z2 - lse;
}

// ---------------- driver ----------------
extern "C" void kernel_launch(void* const* d_in, const int* in_sizes, int n_in,
                              void* d_out, int out_size) {
    const float* x   = (const float*)d_in[0];
    const float* W0  = (const float*)d_in[1];
    const float* al0 = (const float*)d_in[2];
    const float* ar0 = (const float*)d_in[3];
    const float* W1  = (const float*)d_in[4];
    const float* al1 = (const float*)d_in[5];
    const float* ar1 = (const float*)d_in[6];
    const float* W2  = (const float*)d_in[7];
    const float* al2 = (const float*)d_in[8];
    const float* ar2 = (const float*)d_in[9];
    const int*   src = (const int*)d_in[10];
    const int*   dst = (const int*)d_in[11];
    int E = in_sizes[10];
    int N = in_sizes[0] / 100;
    float* out = (float*)d_out;

    float *fs, *a0, *a1, *o2;
    __half* fsh;
    int* cnt;
    cudaGetSymbolAddress((void**)&fs,  g_fs);
    cudaGetSymbolAddress((void**)&a0,  g_act0);
    cudaGetSymbolAddress((void**)&a1,  g_act1);
    cudaGetSymbolAddress((void**)&o2,  g_out2);
    cudaGetSymbolAddress((void**)&fsh, g_fsh);
    cudaGetSymbolAddress((void**)&cnt, g_cnt);

    static cudaStream_t s2 = 0;
    static cudaEvent_t evFork = 0, evJoin = 0, evFork2 = 0, evJoin2 = 0;
    if (s2 == 0) {
        cudaStreamCreateWithFlags(&s2, cudaStreamNonBlocking);
        cudaEventCreateWithFlags(&evFork, cudaEventDisableTiming);
        cudaEventCreateWithFlags(&evJoin, cudaEventDisableTiming);
        cudaEventCreateWithFlags(&evFork2, cudaEventDisableTiming);
        cudaEventCreateWithFlags(&evJoin2, cudaEventDisableTiming);
    }

    const int TB = 256;
    int e4bl = (E / 4 + TB - 1) / TB;
    int wbl = (N * 32 + TB - 1) / TB;
    int mbl = (N + 127) / 128;
    int lbl = (N * 4 + 127) / 128;
    int cbl = (N * 96 + TB - 1) / TB;

    // ---- fork: CSR construction on s2, concurrent with layer-0 gemm/elr ----
    cudaEventRecord(evFork, 0);
    cudaStreamWaitEvent(s2, evFork, 0);
    cudaMemsetAsync(cnt, 0, N * sizeof(int), s2);
    hist_kernel<<<e4bl, TB, 0, s2>>>(dst, E);
    scan_kernel<<<1, 1024, 0, s2>>>(N, E);
    scatter_kernel<<<e4bl, TB, 0, s2>>>(src, dst, E);
    cudaEventRecord(evJoin, s2);

    // Layer 0: x[N,100] -> fs (+fp16 table) -> agg -> act0
    gemm128_kernel<100, 128, true><<<dim3(mbl, 2), 128>>>(x, W0, fs, fsh, N);
    elr_kernel<<<lbl, 128>>>(fs, al0, ar0, N, 32, 128);
    cudaStreamWaitEvent(0, evJoin, 0);
    agg128_kernel<<<wbl, TB>>>(fsh, a0, N, 1);

    // Layer 1
    gemm128_kernel<128, 128, true><<<dim3(mbl, 2), 128>>>(a0, W1, fs, fsh, N);
    elr_kernel<<<lbl, 128>>>(fs, al1, ar1, N, 32, 128);
    agg128_kernel<<<wbl, TB>>>(fsh, a1, N, 1);

    // Layer 2: gemm fp32 -> {elr2 || cvt188} -> agg188 (fp16 gather)
    gemm128_kernel<128, 188, false><<<dim3(mbl, 3), 128>>>(a1, W2, fs, (__half*)0, N);
    cudaEventRecord(evFork2, 0);
    cudaStreamWaitEvent(s2, evFork2, 0);
    cvt188_kernel<<<cbl, TB, 0, s2>>>(fs, fsh, N);
    cudaEventRecord(evJoin2, s2);
    elr_kernel<<<lbl, 128>>>(fs, al2, ar2, N, 47, 188);
    cudaStreamWaitEvent(0, evJoin2, 0);
    agg188_kernel<<<wbl, TB>>>(fsh, o2, N);

    // head mean + log_softmax
    final_kernel<<<wbl, TB>>>(o2, out, N);
}

// round 14
// speedup vs baseline: 1.1186x; 1.1186x over previous
#include <cuda_runtime.h>
#include <math.h>

#define NMAX 50000
#define EMAX 1600000

// ---------------- static device scratch ----------------
__device__ float g_fs[NMAX * 188];     // projected features fs (max F=188)
__device__ float g_act0[NMAX * 128];
__device__ float g_act1[NMAX * 128];
__device__ float g_out2[NMAX * 188];
__device__ float g_el[NMAX * 4];
__device__ float g_er[NMAX * 4];
__device__ float g_e[EMAX * 4];        // exp(edge logit) scratch [E,H] (layer 2 only)
__device__ int   g_csrc[EMAX];
__device__ int   g_rowptr[NMAX + 1];
__device__ int   g_cnt[NMAX];
__device__ int   g_cursor[NMAX];

__device__ __forceinline__ float lrelu(float x) { return x >= 0.f ? x : 0.2f * x; }

// ---- packed fp32x2 FMA (used in aggregation) ----
__device__ __forceinline__ void ffma2(unsigned long long& c, unsigned long long a,
                                      unsigned long long b) {
    asm("fma.rn.f32x2 %0, %1, %2, %0;" : "+l"(c) : "l"(a), "l"(b));
}
__device__ __forceinline__ unsigned long long pk2(float x) {
    unsigned long long r;
    asm("mov.b64 %0, {%1, %1};" : "=l"(r) : "f"(x));
    return r;
}
__device__ __forceinline__ float2 upk2(unsigned long long v) {
    float2 f;
    asm("mov.b64 {%0, %1}, %2;" : "=f"(f.x), "=f"(f.y) : "l"(v));
    return f;
}

__device__ __forceinline__ float to_tf32(float x) {
    float o;
    asm("cvt.rna.tf32.f32 %0, %1;" : "=f"(o) : "f"(x));
    return o;
}

#define WSUM(s) do {                                          \
    _Pragma("unroll")                                         \
    for (int off = 16; off; off >>= 1)                        \
        (s) += __shfl_xor_sync(0xffffffffu, (s), off);        \
} while (0)

// ---------------- CSR construction ----------------
__global__ void hist_kernel(const int* __restrict__ dst, int E) {
    int b = (blockIdx.x * blockDim.x + threadIdx.x) * 4;
    if (b + 3 < E) {
        int4 d = *(const int4*)(dst + b);
        atomicAdd(&g_cnt[d.x], 1);
        atomicAdd(&g_cnt[d.y], 1);
        atomicAdd(&g_cnt[d.z], 1);
        atomicAdd(&g_cnt[d.w], 1);
    } else {
        for (int e = b; e < E; e++) atomicAdd(&g_cnt[dst[e]], 1);
    }
}

__global__ void scan_kernel(int n, int E) {
    const int T = 1024;
    __shared__ int sh[T];
    int tid = threadIdx.x;
    int chunk = (n + T - 1) / T;
    int start = tid * chunk;
    int stop  = min(start + chunk, n);
    int sum = 0;
    for (int i = start; i < stop; i++) sum += g_cnt[i];
    sh[tid] = sum;
    __syncthreads();
    for (int off = 1; off < T; off <<= 1) {
        int v = (tid >= off) ? sh[tid - off] : 0;
        __syncthreads();
        sh[tid] += v;
        __syncthreads();
    }
    int run = sh[tid] - sum;
    for (int i = start; i < stop; i++) {
        g_rowptr[i] = run;
        g_cursor[i] = run;
        run += g_cnt[i];
    }
    if (tid == 0) g_rowptr[n] = E;
}

__global__ void scatter_kernel(const int* __restrict__ src, const int* __restrict__ dst, int E) {
    int b = (blockIdx.x * blockDim.x + threadIdx.x) * 4;
    if (b + 3 < E) {
        int4 s = *(const int4*)(src + b);
        int4 d = *(const int4*)(dst + b);
        int p0 = atomicAdd(&g_cursor[d.x], 1);
        int p1 = atomicAdd(&g_cursor[d.y], 1);
        int p2 = atomicAdd(&g_cursor[d.z], 1);
        int p3 = atomicAdd(&g_cursor[d.w], 1);
        g_csrc[p0] = s.x; g_csrc[p1] = s.y;
        g_csrc[p2] = s.z; g_csrc[p3] = s.w;
    } else {
        for (int e = b; e < E; e++) {
            int p = atomicAdd(&g_cursor[dst[e]], 1);
            g_csrc[p] = src[e];
        }
    }
}

// ---------------- tf32 tensor-core GEMM: out[n,F] = A[n,K] @ W[K,F] ----------------
// BM=128, BN=64, BK=16, 256 threads (8 warps: 4m x 2n), warp tile 32x32.
// Two-stage smem double buffer; tf32 (rna) inputs, fp32 accumulate.
template <int K, int F>
__global__ void gemmT_kernel(const float* __restrict__ A, const float* __restrict__ W,
                             float* __restrict__ out, int n) {
    static_assert(K % 4 == 0 && F % 4 == 0, "quad-aligned");
    __shared__ float As[2][16][132];   // [stage][k][m], pad 132 (<=2-way conflicts)
    __shared__ float Ws[2][16][72];    // [stage][k][f], pad 72 (conflict-free frag loads)
    const int t    = threadIdx.x;
    const int lane = t & 31;
    const int warp = t >> 5;
    const int wm = warp & 3;           // 4 m-warps
    const int wn = warp >> 2;          // 2 n-warps
    const int gid = lane >> 2, tig = lane & 3;
    const int m0 = blockIdx.x * 128;
    const int f0 = blockIdx.y * 64;
    const int KT = (K + 15) / 16;

    float acc[2][4][4];
#pragma unroll
    for (int ma = 0; ma < 2; ma++)
#pragma unroll
        for (int na = 0; na < 4; na++)
#pragma unroll
            for (int c = 0; c < 4; c++) acc[ma][na][c] = 0.f;

    float4 rA[2], rW;

    auto loadG = [&](int k0) {
#pragma unroll
        for (int i = 0; i < 2; i++) {
            int q = i * 256 + t;           // 0..511 quads of A tile (128x16)
            int m = q >> 2, kq = q & 3;
            int row = m0 + m, k = k0 + kq * 4;
            float4 v = make_float4(0.f, 0.f, 0.f, 0.f);
            if (row < n && k < K) v = *(const float4*)(A + (long)row * K + k);
            rA[i] = v;
        }
        {
            int krow = t >> 4, fq = t & 15;   // 256 quads of W tile (16x64)
            int k = k0 + krow, f = f0 + fq * 4;
            float4 v = make_float4(0.f, 0.f, 0.f, 0.f);
            if (k < K && f < F) v = *(const float4*)(W + (long)k * F + f);
            rW = v;
        }
    };
    auto storeS = [&](int s) {
#pragma unroll
        for (int i = 0; i < 2; i++) {
            int q = i * 256 + t;
            int m = q >> 2, kq = q & 3;
            As[s][kq * 4 + 0][m] = to_tf32(rA[i].x);
            As[s][kq * 4 + 1][m] = to_tf32(rA[i].y);
            As[s][kq * 4 + 2][m] = to_tf32(rA[i].z);
            As[s][kq * 4 + 3][m] = to_tf32(rA[i].w);
        }
        int krow = t >> 4, fq = t & 15;
        float4 w4 = make_float4(to_tf32(rW.x), to_tf32(rW.y), to_tf32(rW.z), to_tf32(rW.w));
        *(float4*)&Ws[s][krow][fq * 4] = w4;
    };

    loadG(0);
    storeS(0);
    __syncthreads();
    for (int ko = 0; ko < KT; ko++) {
        if (ko + 1 < KT) loadG((ko + 1) * 16);
        int s = ko & 1;
#pragma unroll
        for (int ka = 0; ka < 2; ka++) {
            int kk = ka * 8;
            unsigned a[2][4], b[4][2];
#pragma unroll
            for (int ma = 0; ma < 2; ma++) {
                int mrow = wm * 32 + ma * 16 + gid;
                a[ma][0] = __float_as_uint(As[s][kk + tig    ][mrow]);
                a[ma][1] = __float_as_uint(As[s][kk + tig    ][mrow + 8]);
                a[ma][2] = __float_as_uint(As[s][kk + tig + 4][mrow]);
                a[ma][3] = __float_as_uint(As[s][kk + tig + 4][mrow + 8]);
            }
#pragma unroll
            for (int na = 0; na < 4; na++) {
                int ncol = wn * 32 + na * 8 + gid;
                b[na][0] = __float_as_uint(Ws[s][kk + tig    ][ncol]);
                b[na][1] = __float_as_uint(Ws[s][kk + tig + 4][ncol]);
            }
#pragma unroll
            for (int ma = 0; ma < 2; ma++)
#pragma unroll
                for (int na = 0; na < 4; na++)
                    asm volatile(
                        "mma.sync.aligned.m16n8k8.row.col.f32.tf32.tf32.f32 "
                        "{%0,%1,%2,%3}, {%4,%5,%6,%7}, {%8,%9}, {%0,%1,%2,%3};"
                        : "+f"(acc[ma][na][0]), "+f"(acc[ma][na][1]),
                          "+f"(acc[ma][na][2]), "+f"(acc[ma][na][3])
                        : "r"(a[ma][0]), "r"(a[ma][1]), "r"(a[ma][2]), "r"(a[ma][3]),
                          "r"(b[na][0]), "r"(b[na][1]));
        }
        __syncthreads();
        if (ko + 1 < KT) {
            storeS((ko + 1) & 1);
            __syncthreads();
        }
    }

    // epilogue: c0,c1 = row gid, cols 2*tig,2*tig+1; c2,c3 = row gid+8
#pragma unroll
    for (int ma = 0; ma < 2; ma++) {
        int r0 = m0 + wm * 32 + ma * 16 + gid;
#pragma unroll
        for (int na = 0; na < 4; na++) {
            int c = f0 + wn * 32 + na * 8 + 2 * tig;
            if (c < F) {     // F even, c even -> covers c+1
                if (r0 < n) {
                    float2 v = make_float2(acc[ma][na][0], acc[ma][na][1]);
                    *(float2*)(out + (long)r0 * F + c) = v;
                }
                if (r0 + 8 < n) {
                    float2 v = make_float2(acc[ma][na][2], acc[ma][na][3]);
                    *(float2*)(out + (long)(r0 + 8) * F + c) = v;
                }
            }
        }
    }
}

// ---------------- el/er ----------------
__global__ void elr_kernel(const float* __restrict__ fs, const float* __restrict__ al,
                           const float* __restrict__ ar, int n, int Dd, int F) {
    int idx = blockIdx.x * blockDim.x + threadIdx.x;
    if (idx >= n * 4) return;
    int node = idx >> 2, h = idx & 3;
    const float* row = fs + node * F + h * Dd;
    const float* a1  = al + h * Dd;
    const float* a2  = ar + h * Dd;
    float se = 0.f, sr = 0.f;
#pragma unroll 8
    for (int d = 0; d < Dd; d++) {
        float v = row[d];
        se = fmaf(v, a1[d], se);
        sr = fmaf(v, a2[d], sr);
    }
    g_el[idx] = se;
    g_er[idx] = sr;
}

// ---------------- fused single-pass aggregation, F=128 (layers 0/1) ----------------
__global__ void agg128_kernel(const float* __restrict__ fs, float* __restrict__ out,
                              int n, int dorelu) {
    int warp = (blockIdx.x * blockDim.x + threadIdx.x) >> 5;
    int lane = threadIdx.x & 31;
    if (warp >= n) return;
    int beg = g_rowptr[warp], end = g_rowptr[warp + 1];
    int h = lane >> 3;
    float er_h = g_er[warp * 4 + h];

    float s = 0.f;
    unsigned long long acc2[2] = {0ull, 0ull};
    int j = beg;
    for (; j + 4 <= end; j += 4) {
        int sc[4];
#pragma unroll
        for (int q = 0; q < 4; q++) sc[q] = g_csrc[j + q];
        float el[4];
#pragma unroll
        for (int q = 0; q < 4; q++) el[q] = g_el[sc[q] * 4 + h];
        ulonglong2 v[4];
#pragma unroll
        for (int q = 0; q < 4; q++) v[q] = *(const ulonglong2*)(fs + sc[q] * 128 + lane * 4);
#pragma unroll
        for (int q = 0; q < 4; q++) {
            float x = __expf(lrelu(el[q] + er_h));
            s += x;
            unsigned long long pa = pk2(x);
            ffma2(acc2[0], pa, v[q].x);
            ffma2(acc2[1], pa, v[q].y);
        }
    }
    for (; j < end; j++) {
        int sc = g_csrc[j];
        float x = __expf(lrelu(g_el[sc * 4 + h] + er_h));
        s += x;
        unsigned long long pa = pk2(x);
        ulonglong2 v = *(const ulonglong2*)(fs + sc * 128 + lane * 4);
        ffma2(acc2[0], pa, v.x);
        ffma2(acc2[1], pa, v.y);
    }
    float ish = s > 0.f ? 1.f / s : 0.f;
    float2 lo = upk2(acc2[0]);
    float2 hi = upk2(acc2[1]);
    float4 acc = make_float4(lo.x * ish, lo.y * ish, hi.x * ish, hi.y * ish);
    if (dorelu) {
        acc.x = fmaxf(acc.x, 0.f); acc.y = fmaxf(acc.y, 0.f);
        acc.z = fmaxf(acc.z, 0.f); acc.w = fmaxf(acc.w, 0.f);
    }
    *(float4*)(out + warp * 128 + lane * 4) = acc;
}

// ---------------- aggregation, F=188 (layer 2): two-phase ----------------
__global__ void agg188_kernel(const float* __restrict__ fs, float* __restrict__ out, int n) {
    int warp = (blockIdx.x * blockDim.x + threadIdx.x) >> 5;
    int lane = threadIdx.x & 31;
    if (warp >= n) return;
    int beg = g_rowptr[warp], end = g_rowptr[warp + 1];
    float4 er4 = *(const float4*)(g_er + warp * 4);

    float s0 = 0.f, s1 = 0.f, s2 = 0.f, s3 = 0.f;
    for (int j = beg + lane; j < end; j += 32) {
        int sc = g_csrc[j];
        float4 el4 = *(const float4*)(g_el + sc * 4);
        float x0 = __expf(lrelu(el4.x + er4.x));
        float x1 = __expf(lrelu(el4.y + er4.y));
        float x2 = __expf(lrelu(el4.z + er4.z));
        float x3 = __expf(lrelu(el4.w + er4.w));
        *(float4*)(g_e + 4 * j) = make_float4(x0, x1, x2, x3);
        s0 += x0; s1 += x1; s2 += x2; s3 += x3;
    }
    WSUM(s0); WSUM(s1); WSUM(s2); WSUM(s3);
    __syncwarp();

    float i0 = s0 > 0.f ? 1.f / s0 : 0.f;
    float i1 = s1 > 0.f ? 1.f / s1 : 0.f;
    float i2 = s2 > 0.f ? 1.f / s2 : 0.f;
    float i3 = s3 > 0.f ? 1.f / s3 : 0.f;

    float acc[6];
    int   hh[6];
    bool  vld[6];
#pragma unroll
    for (int t = 0; t < 6; t++) {
        int f = lane + 32 * t;
        vld[t] = f < 188;
        hh[t]  = vld[t] ? f / 47 : 0;
        acc[t] = 0.f;
    }
    int j = beg;
    for (; j + 2 <= end; j += 2) {
        int sc0 = g_csrc[j];
        int sc1 = g_csrc[j + 1];
        float4 av0 = *(const float4*)(g_e + 4 * j);
        float4 av1 = *(const float4*)(g_e + 4 * j + 4);
        const float* r0 = fs + sc0 * 188;
        const float* r1 = fs + sc1 * 188;
#pragma unroll
        for (int t = 0; t < 6; t++) {
            if (vld[t]) {
                float a0 = hh[t] == 0 ? av0.x : hh[t] == 1 ? av0.y : hh[t] == 2 ? av0.z : av0.w;
                float a1 = hh[t] == 0 ? av1.x : hh[t] == 1 ? av1.y : hh[t] == 2 ? av1.z : av1.w;
                acc[t] = fmaf(a0, r0[lane + 32 * t], acc[t]);
                acc[t] = fmaf(a1, r1[lane + 32 * t], acc[t]);
            }
        }
    }
    if (j < end) {
        int sc = g_csrc[j];
        float4 av = *(const float4*)(g_e + 4 * j);
        const float* row = fs + sc * 188;
#pragma unroll
        for (int t = 0; t < 6; t++) {
            if (vld[t]) {
                float a = hh[t] == 0 ? av.x : hh[t] == 1 ? av.y : hh[t] == 2 ? av.z : av.w;
                acc[t] = fmaf(a, row[lane + 32 * t], acc[t]);
            }
        }
    }
#pragma unroll
    for (int t = 0; t < 6; t++) {
        if (vld[t]) {
            float ish = hh[t] == 0 ? i0 : hh[t] == 1 ? i1 : hh[t] == 2 ? i2 : i3;
            out[warp * 188 + lane + 32 * t] = acc[t] * ish;
        }
    }
}

// ---------------- head mean + log_softmax ----------------
__global__ void final_kernel(const float* __restrict__ o2, float* __restrict__ out, int n) {
    int warp = (blockIdx.x * blockDim.x + threadIdx.x) >> 5;
    int lane = threadIdx.x & 31;
    if (warp >= n) return;
    const float* base = o2 + warp * 188;
    int c1 = lane;
    int c2 = lane + 32;
    bool v2 = c2 < 47;
    float z1 = 0.25f * (base[c1] + base[47 + c1] + base[94 + c1] + base[141 + c1]);
    float z2 = v2 ? 0.25f * (base[c2] + base[47 + c2] + base[94 + c2] + base[141 + c2]) : -INFINITY;
    float mx = fmaxf(z1, z2);
#pragma unroll
    for (int off = 16; off; off >>= 1)
        mx = fmaxf(mx, __shfl_xor_sync(0xffffffffu, mx, off));
    float se = __expf(z1 - mx) + (v2 ? __expf(z2 - mx) : 0.f);
#pragma unroll
    for (int off = 16; off; off >>= 1)
        se += __shfl_xor_sync(0xffffffffu, se, off);
    float lse = mx + logf(se);
    out[warp * 47 + c1] = z1 - lse;
    if (v2) out[warp * 47 + c2] = z2 - lse;
}

// ---------------- driver ----------------
extern "C" void kernel_launch(void* const* d_in, const int* in_sizes, int n_in,
                              void* d_out, int out_size) {
    const float* x   = (const float*)d_in[0];
    const float* W0  = (const float*)d_in[1];
    const float* al0 = (const float*)d_in[2];
    const float* ar0 = (const float*)d_in[3];
    const float* W1  = (const float*)d_in[4];
    const float* al1 = (const float*)d_in[5];
    const float* ar1 = (const float*)d_in[6];
    const float* W2  = (const float*)d_in[7];
    const float* al2 = (const float*)d_in[8];
    const float* ar2 = (const float*)d_in[9];
    const int*   src = (const int*)d_in[10];
    const int*   dst = (const int*)d_in[11];
    int E = in_sizes[10];
    int N = in_sizes[0] / 100;
    float* out = (float*)d_out;

    float *fs, *a0, *a1, *o2;
    int* cnt;
    cudaGetSymbolAddress((void**)&fs, g_fs);
    cudaGetSymbolAddress((void**)&a0, g_act0);
    cudaGetSymbolAddress((void**)&a1, g_act1);
    cudaGetSymbolAddress((void**)&o2, g_out2);
    cudaGetSymbolAddress((void**)&cnt, g_cnt);

    static cudaStream_t s2 = 0;
    static cudaEvent_t evFork = 0, evJoin = 0;
    if (s2 == 0) {
        cudaStreamCreateWithFlags(&s2, cudaStreamNonBlocking);
        cudaEventCreateWithFlags(&evFork, cudaEventDisableTiming);
        cudaEventCreateWithFlags(&evJoin, cudaEventDisableTiming);
    }

    const int TB = 256;
    int e4bl = (E / 4 + TB - 1) / TB;
    int wbl = (N * 32 + TB - 1) / TB;
    int mbl = (N + 127) / 128;
    int lbl = (N * 4 + 127) / 128;

    // ---- fork: CSR construction on s2, concurrent with layer-0 gemm/elr ----
    cudaEventRecord(evFork, 0);
    cudaStreamWaitEvent(s2, evFork, 0);
    cudaMemsetAsync(cnt, 0, N * sizeof(int), s2);
    hist_kernel<<<e4bl, TB, 0, s2>>>(dst, E);
    scan_kernel<<<1, 1024, 0, s2>>>(N, E);
    scatter_kernel<<<e4bl, TB, 0, s2>>>(src, dst, E);
    cudaEventRecord(evJoin, s2);

    // Layer 0: x[N,100] -> fs[N,128] -> agg -> act0[N,128]
    gemmT_kernel<100, 128><<<dim3(mbl, 2), 256>>>(x, W0, fs, N);
    elr_kernel<<<lbl, 128>>>(fs, al0, ar0, N, 32, 128);
    cudaStreamWaitEvent(0, evJoin, 0);
    agg128_kernel<<<wbl, TB>>>(fs, a0, N, 1);

    // Layer 1
    gemmT_kernel<128, 128><<<dim3(mbl, 2), 256>>>(a0, W1, fs, N);
    elr_kernel<<<lbl, 128>>>(fs, al1, ar1, N, 32, 128);
    agg128_kernel<<<wbl, TB>>>(fs, a1, N, 1);

    // Layer 2
    gemmT_kernel<128, 188><<<dim3(mbl, 3), 256>>>(a1, W2, fs, N);
    elr_kernel<<<lbl, 128>>>(fs, al2, ar2, N, 47, 188);
    agg188_kernel<<<wbl, TB>>>(fs, o2, N);

    // head mean + log_softmax
    final_kernel<<<wbl, TB>>>(o2, out, N);
}